// round 1
// baseline (speedup 1.0000x reference)
#include <cuda_runtime.h>
#include <math.h>

#define BATCH 2
#define NSEQ  2048
#define DIM   2048
#define NH    16
#define DH    128
#define INNER 2048
#define QK_SCALE 0.08838834764831845f  /* 128^-0.5 */

// Scratch (static device allocations are allowed; cudaMalloc is not)
__device__ float g_qproj[BATCH * NSEQ * INNER];   // [b, n, h*d]  (RoPE'd + scaled in place)
__device__ float g_kv[BATCH * NSEQ * 2 * DH];     // [b, n, 256]  (k RoPE'd in place, v raw)
__device__ float g_attn[BATCH * NSEQ * INNER];    // [b, n, h*d]  attention output

// ---------------------------------------------------------------------------
// Tiled fp32 GEMM: C[M,N] = A[M,K] @ B[K,N], all row-major.
// 128x128 block tile, BK=16, 256 threads, 8x8 per thread with STRIDED
// thread->element mapping (tx + 16*j) so compute-phase LDS are broadcast
// (A) or stride-1 (B): conflict-free.
// Requires M%128==0, N%128==0, K%16==0 (true for all our shapes).
// ---------------------------------------------------------------------------
__global__ __launch_bounds__(256) void gemm_f32(
    const float* __restrict__ A, const float* __restrict__ Bm,
    float* __restrict__ C, int M, int N, int K)
{
    __shared__ float As[16][132];   // [k][m], padded
    __shared__ float Bs[16][128];   // [k][n]
    const int tid = threadIdx.x;
    const int tx = tid & 15, ty = tid >> 4;
    const int m0 = blockIdx.y << 7, n0 = blockIdx.x << 7;

    float acc[8][8];
#pragma unroll
    for (int i = 0; i < 8; i++)
#pragma unroll
        for (int j = 0; j < 8; j++) acc[i][j] = 0.f;

    for (int k0 = 0; k0 < K; k0 += 16) {
        // A tile 128x16: coalesced float4 loads, transpose into As
#pragma unroll
        for (int t = 0; t < 2; t++) {
            int idx = tid + (t << 8);           // 0..511
            int m = idx >> 2, j4 = idx & 3;
            float4 v = *(const float4*)&A[(size_t)(m0 + m) * K + k0 + (j4 << 2)];
            As[(j4 << 2) + 0][m] = v.x;
            As[(j4 << 2) + 1][m] = v.y;
            As[(j4 << 2) + 2][m] = v.z;
            As[(j4 << 2) + 3][m] = v.w;
        }
        // B tile 16x128: coalesced float4, natural layout
#pragma unroll
        for (int t = 0; t < 2; t++) {
            int idx = tid + (t << 8);
            int r = idx >> 5, c4 = idx & 31;
            *(float4*)&Bs[r][c4 << 2] =
                *(const float4*)&Bm[(size_t)(k0 + r) * N + n0 + (c4 << 2)];
        }
        __syncthreads();
#pragma unroll 4
        for (int kk = 0; kk < 16; kk++) {
            float a[8], b[8];
#pragma unroll
            for (int i = 0; i < 8; i++) a[i] = As[kk][ty + (i << 4)];
#pragma unroll
            for (int j = 0; j < 8; j++) b[j] = Bs[kk][tx + (j << 4)];
#pragma unroll
            for (int i = 0; i < 8; i++)
#pragma unroll
                for (int j = 0; j < 8; j++) acc[i][j] = fmaf(a[i], b[j], acc[i][j]);
        }
        __syncthreads();
    }
#pragma unroll
    for (int i = 0; i < 8; i++) {
        float* crow = &C[(size_t)(m0 + ty + (i << 4)) * N + n0];
#pragma unroll
        for (int j = 0; j < 8; j++) crow[tx + (j << 4)] = acc[i][j];
    }
}

// ---------------------------------------------------------------------------
// RoPE (in place): q heads get rotated AND scaled by 1/sqrt(d); k rotated.
// One thread per (b, n, unit, pair): unit 0..15 = q heads, unit 16 = k.
// out[i]    = x1*cos - x2*sin
// out[i+64] = x2*cos + x1*sin      with angle = n * 10000^(-2i/128)
// ---------------------------------------------------------------------------
__global__ void rope_kernel()
{
    int t = blockIdx.x * blockDim.x + threadIdx.x;
    const int TOT = BATCH * NSEQ * 17 * 64;
    if (t >= TOT) return;
    int pair = t & 63;
    int unit = (t >> 6) % 17;
    int rest = t / (64 * 17);
    int n = rest % NSEQ;
    int b = rest / NSEQ;

    float invf = powf(10000.f, -(float)(pair << 1) * (1.f / 128.f));
    float ang = (float)n * invf;
    float s, c;
    sincosf(ang, &s, &c);

    float* base;
    float sc;
    if (unit < NH) {
        base = g_qproj + ((size_t)(b * NSEQ + n)) * INNER + unit * DH;
        sc = QK_SCALE;
    } else {
        base = g_kv + ((size_t)(b * NSEQ + n)) * (2 * DH);
        sc = 1.f;
    }
    float x1 = base[pair], x2 = base[pair + 64];
    base[pair]      = (x1 * c - x2 * s) * sc;
    base[pair + 64] = (x2 * c + x1 * s) * sc;
}

// ---------------------------------------------------------------------------
// Causal flash attention, multi-query (one K/V per batch, 16 q heads).
// Tile: BM=BN=128, d=128. 256 threads, 8x8 S micro-tile per thread with
// strided mapping: rows ty+16i, cols tx+16j. Online softmax (matches ref:
// subtract running max, exp, normalize at end).
// Shared: q_s [128kk][129] | kp_s [128][129] (K tile, then P tile) | v_s [128][128]
// ---------------------------------------------------------------------------
#define FLASH_SMEM ((2 * 128 * 129 + 128 * 128) * 4)

extern __shared__ float fsm[];
__global__ __launch_bounds__(256, 1) void flash_kernel()
{
    float* q_s  = fsm;                   // kk-major, pitch 129
    float* kp_s = fsm + 128 * 129;       // K tile (kk-major), later P tile (c-major)
    float* v_s  = fsm + 2 * 128 * 129;   // [c][d], pitch 128

    const int tid = threadIdx.x, tx = tid & 15, ty = tid >> 4;
    const int ib = blockIdx.x, h = blockIdx.y, b = blockIdx.z;
    const int r0 = ib << 7;
    const float* qg  = g_qproj + (size_t)b * NSEQ * INNER + h * DH;
    const float* kvg = g_kv + (size_t)b * NSEQ * (2 * DH);

    // Load Q tile (once): rows r0..r0+127, 128 dims, kk-major in shared
#pragma unroll
    for (int t = 0; t < 16; t++) {
        int idx = tid + (t << 8);
        int r = idx >> 5, j = idx & 31;
        float4 v = *(const float4*)&qg[(size_t)(r0 + r) * INNER + (j << 2)];
        q_s[((j << 2) + 0) * 129 + r] = v.x;
        q_s[((j << 2) + 1) * 129 + r] = v.y;
        q_s[((j << 2) + 2) * 129 + r] = v.z;
        q_s[((j << 2) + 3) * 129 + r] = v.w;
    }

    float acc[8][8], m_i[8], l_i[8];
#pragma unroll
    for (int i = 0; i < 8; i++) {
        m_i[i] = -INFINITY; l_i[i] = 0.f;
#pragma unroll
        for (int j = 0; j < 8; j++) acc[i][j] = 0.f;
    }

    for (int jb = 0; jb <= ib; jb++) {
        __syncthreads();  // prior iter's P/V readers done before overwrite
        const int c0 = jb << 7;
        // Load K (kk-major into kp_s) and V (natural into v_s)
#pragma unroll
        for (int t = 0; t < 16; t++) {
            int idx = tid + (t << 8);
            int cc = idx >> 5, j = idx & 31;
            float4 v = *(const float4*)&kvg[(size_t)(c0 + cc) * 256 + (j << 2)];
            kp_s[((j << 2) + 0) * 129 + cc] = v.x;
            kp_s[((j << 2) + 1) * 129 + cc] = v.y;
            kp_s[((j << 2) + 2) * 129 + cc] = v.z;
            kp_s[((j << 2) + 3) * 129 + cc] = v.w;
            float4 w = *(const float4*)&kvg[(size_t)(c0 + cc) * 256 + 128 + (j << 2)];
            *(float4*)&v_s[cc * 128 + (j << 2)] = w;
        }
        __syncthreads();

        // S = Q K^T  (128x128x128)
        float s[8][8];
#pragma unroll
        for (int i = 0; i < 8; i++)
#pragma unroll
            for (int j = 0; j < 8; j++) s[i][j] = 0.f;
#pragma unroll 2
        for (int kk = 0; kk < 128; kk++) {
            float a[8], bb[8];
#pragma unroll
            for (int i = 0; i < 8; i++) a[i] = q_s[kk * 129 + ty + (i << 4)];
#pragma unroll
            for (int j = 0; j < 8; j++) bb[j] = kp_s[kk * 129 + tx + (j << 4)];
#pragma unroll
            for (int i = 0; i < 8; i++)
#pragma unroll
                for (int j = 0; j < 8; j++) s[i][j] = fmaf(a[i], bb[j], s[i][j]);
        }
        // Causal mask (diagonal block only; r0 == c0 there)
        if (jb == ib) {
#pragma unroll
            for (int i = 0; i < 8; i++)
#pragma unroll
                for (int j = 0; j < 8; j++)
                    if (tx + (j << 4) > ty + (i << 4)) s[i][j] = -1e30f;
        }
        // Online softmax update (row reductions across the 16 tx lanes)
#pragma unroll
        for (int i = 0; i < 8; i++) {
            float rm = s[i][0];
#pragma unroll
            for (int j = 1; j < 8; j++) rm = fmaxf(rm, s[i][j]);
#pragma unroll
            for (int o = 1; o < 16; o <<= 1)
                rm = fmaxf(rm, __shfl_xor_sync(0xffffffffu, rm, o));
            float mn = fmaxf(m_i[i], rm);
            float alpha = __expf(m_i[i] - mn);   // 0 on first block (m=-inf)
            m_i[i] = mn;
            float sum = 0.f;
#pragma unroll
            for (int j = 0; j < 8; j++) {
                float p = __expf(s[i][j] - mn);
                s[i][j] = p;
                sum += p;
            }
#pragma unroll
            for (int o = 1; o < 16; o <<= 1)
                sum += __shfl_xor_sync(0xffffffffu, sum, o);
            l_i[i] = l_i[i] * alpha + sum;
#pragma unroll
            for (int j = 0; j < 8; j++) acc[i][j] *= alpha;
        }
        __syncthreads();              // everyone done reading kp_s as K
        // Stage P into kp_s as [c][r] (pitch 129; stride-tx writes, conflict-free)
#pragma unroll
        for (int j = 0; j < 8; j++)
#pragma unroll
            for (int i = 0; i < 8; i++)
                kp_s[(tx + (j << 4)) * 129 + ty + (i << 4)] = s[i][j];
        __syncthreads();
        // O += P @ V   (128x128x128)
#pragma unroll 2
        for (int c = 0; c < 128; c++) {
            float pv[8], vv[8];
#pragma unroll
            for (int i = 0; i < 8; i++) pv[i] = kp_s[c * 129 + ty + (i << 4)];
#pragma unroll
            for (int d = 0; d < 8; d++) vv[d] = v_s[c * 128 + tx + (d << 4)];
#pragma unroll
            for (int i = 0; i < 8; i++)
#pragma unroll
                for (int d = 0; d < 8; d++) acc[i][d] = fmaf(pv[i], vv[d], acc[i][d]);
        }
    }
    // Epilogue: normalize and write [b, n, h*d]
    float* og = g_attn + (size_t)b * NSEQ * INNER + h * DH;
#pragma unroll
    for (int i = 0; i < 8; i++) {
        float inv = 1.f / l_i[i];
        float* orow = &og[(size_t)(r0 + ty + (i << 4)) * INNER];
#pragma unroll
        for (int d = 0; d < 8; d++) orow[tx + (d << 4)] = acc[i][d] * inv;
    }
}

// ---------------------------------------------------------------------------
extern "C" void kernel_launch(void* const* d_in, const int* in_sizes, int n_in,
                              void* d_out, int out_size)
{
    (void)in_sizes; (void)n_in; (void)out_size;
    const float* x    = (const float*)d_in[0];
    const float* Wq   = (const float*)d_in[1];
    const float* Wkv  = (const float*)d_in[2];
    const float* Wout = (const float*)d_in[3];
    float* out = (float*)d_out;

    void *pq = nullptr, *pkv = nullptr, *pattn = nullptr;
    cudaGetSymbolAddress(&pq, g_qproj);
    cudaGetSymbolAddress(&pkv, g_kv);
    cudaGetSymbolAddress(&pattn, g_attn);

    cudaFuncSetAttribute(flash_kernel,
                         cudaFuncAttributeMaxDynamicSharedMemorySize, FLASH_SMEM);

    const int M = BATCH * NSEQ;  // 4096
    dim3 blk(256);

    // 1) q = x @ Wq   [4096,2048] x [2048,2048]
    gemm_f32<<<dim3(INNER / 128, M / 128), blk>>>(x, Wq, (float*)pq, M, INNER, DIM);
    // 2) kv = x @ Wkv [4096,2048] x [2048,256]
    gemm_f32<<<dim3((2 * DH) / 128, M / 128), blk>>>(x, Wkv, (float*)pkv, M, 2 * DH, DIM);
    // 3) RoPE in place (+ q scaling)
    {
        int tot = BATCH * NSEQ * 17 * 64;
        rope_kernel<<<(tot + 255) / 256, 256>>>();
    }
    // 4) causal flash attention
    flash_kernel<<<dim3(NSEQ / 128, NH, BATCH), blk, FLASH_SMEM>>>();
    // 5) out = attn @ Wout
    gemm_f32<<<dim3(DIM / 128, M / 128), blk>>>((const float*)pattn, Wout, out, M, DIM, INNER);
}

// round 3
// speedup vs baseline: 1.7289x; 1.7289x over previous
#include <cuda_runtime.h>
#include <cuda_bf16.h>
#include <math.h>
#include <cstdint>

#define BATCH 2
#define NSEQ  2048
#define DIM   2048
#define NH    16
#define DH    128
#define INNER 2048
#define KDIM  2048
#define QK_SCALE 0.08838834764831845f  /* 128^-0.5 */

// ---------------------------------------------------------------------------
// Scratch (static device allocations allowed; cudaMalloc is not)
// ---------------------------------------------------------------------------
__device__ float g_qproj[BATCH * NSEQ * INNER];
__device__ float g_kv[BATCH * NSEQ * 2 * DH];
__device__ float g_attn[BATCH * NSEQ * INNER];
__device__ float g_WqT[DIM * INNER];
__device__ float g_WkvT[2 * DH * DIM];
__device__ float g_WoutT[DIM * INNER];

__device__ __forceinline__ uint32_t smem_u32(const void* p) {
    uint32_t a;
    asm("{ .reg .u64 t; cvta.to.shared.u64 t, %1; cvt.u32.u64 %0, t; }" : "=r"(a) : "l"(p));
    return a;
}
__device__ __forceinline__ void ldmat_x4(uint32_t* r, uint32_t addr) {
    asm volatile("ldmatrix.sync.aligned.m8n8.x4.shared.b16 {%0,%1,%2,%3}, [%4];"
                 : "=r"(r[0]), "=r"(r[1]), "=r"(r[2]), "=r"(r[3]) : "r"(addr));
}
__device__ __forceinline__ void mma_bf16(float* d, const uint32_t* a, const uint32_t* b) {
    asm volatile(
        "mma.sync.aligned.m16n8k16.row.col.f32.bf16.bf16.f32 "
        "{%0,%1,%2,%3}, {%4,%5,%6,%7}, {%8,%9}, {%0,%1,%2,%3};"
        : "+f"(d[0]), "+f"(d[1]), "+f"(d[2]), "+f"(d[3])
        : "r"(a[0]), "r"(a[1]), "r"(a[2]), "r"(a[3]), "r"(b[0]), "r"(b[1]));
}
// pack two floats to bf16x2 (x0 -> low half, x1 -> high half)
__device__ __forceinline__ uint32_t pack_bf16x2(float x0, float x1) {
    uint32_t r;
    asm("cvt.rn.bf16x2.f32 %0, %1, %2;" : "=r"(r) : "f"(x1), "f"(x0));
    return r;
}
// split a float pair into hi/lo bf16x2 words
__device__ __forceinline__ void split_pair(float x0, float x1, uint32_t& hi, uint32_t& lo) {
    hi = pack_bf16x2(x0, x1);
    float h0 = __uint_as_float(hi << 16);
    float h1 = __uint_as_float(hi & 0xffff0000u);
    lo = pack_bf16x2(x0 - h0, x1 - h1);
}

// ---------------------------------------------------------------------------
// Weight transpose: in [R, C] -> out [C, R]
// ---------------------------------------------------------------------------
__global__ void transpose_kernel(const float* __restrict__ in, float* __restrict__ out,
                                 int R, int C)
{
    __shared__ float t[32][33];
    int c0 = blockIdx.x << 5, r0 = blockIdx.y << 5;
    int x = threadIdx.x, y = threadIdx.y;
#pragma unroll
    for (int i = 0; i < 32; i += 8)
        t[y + i][x] = in[(size_t)(r0 + y + i) * C + c0 + x];
    __syncthreads();
#pragma unroll
    for (int i = 0; i < 32; i += 8)
        out[(size_t)(c0 + y + i) * R + r0 + x] = t[x][y + i];
}

// ---------------------------------------------------------------------------
// Split-bf16 mma.sync GEMM: C[M,N] = A[M,2048] @ BT[N,2048]^T
// CTA tile 128x128, BK=32, 256 threads (8 warps, 4x2 grid of 32x64 warp tiles).
// SMEM per stage: Ah|Al ([m 0..127][k 0..31] bf16, 80B pitch) and Bh|Bl
// ([n][k], same). Pitch 80B => ldmatrix reads conflict-free (bank stride 20).
// 3 MMAs per logical MMA: hi*hi + hi*lo + lo*hi  (error ~2^-17).
// ---------------------------------------------------------------------------
#define PITCHB 80
#define BUF_BYTES (128 * PITCHB)          /* 10240 */
#define STAGE_BYTES (4 * BUF_BYTES)       /* Ah Al Bh Bl = 40960 */
#define GEMM_SMEM (2 * STAGE_BYTES)       /* 81920 */
#define NKIT (KDIM / 32)                  /* 64 */

extern __shared__ float fsm[];

__global__ __launch_bounds__(256, 1) void gemm_mma(
    const float* __restrict__ A, const float* __restrict__ BT,
    float* __restrict__ C, int M, int N)
{
    char* sm = (char*)fsm;
    const uint32_t smb = smem_u32(sm);
    const int tid = threadIdx.x;
    const int wid = tid >> 5, L = tid & 31;
    const int wm = wid & 3, wn = wid >> 2;
    const int m0 = blockIdx.y << 7, n0 = blockIdx.x << 7;

    const int ldr = tid >> 3;        // 0..31 -> rows (tid..): idx scheme below
    const int ldc = tid & 7;         // float4 col 0..7

    float acc[2][8][4];
#pragma unroll
    for (int mi = 0; mi < 2; mi++)
#pragma unroll
        for (int ni = 0; ni < 8; ni++)
#pragma unroll
            for (int e = 0; e < 4; e++) acc[mi][ni][e] = 0.f;

    float4 va[4], vb[4];

    // ---- global load of one k-chunk into registers ----
    auto ldg_stage = [&](int kc) {
#pragma unroll
        for (int t = 0; t < 4; t++) {
            int r = ldr + (t << 5);                 // 0..127
            const float* pa = &A[(size_t)(m0 + r) * KDIM + (kc << 5) + (ldc << 2)];
            const float* pb = &BT[(size_t)(n0 + r) * KDIM + (kc << 5) + (ldc << 2)];
            va[t] = *(const float4*)pa;
            vb[t] = *(const float4*)pb;
        }
    };
    // ---- split + store to smem stage ----
    auto sts_stage = [&](int stg) {
        char* base = sm + stg * STAGE_BYTES;
#pragma unroll
        for (int t = 0; t < 4; t++) {
            int r = ldr + (t << 5);
            uint32_t off = (uint32_t)r * PITCHB + (ldc << 3);   // 8 bytes per float4->bf16x4
            uint32_t h0, l0, h1, l1;
            split_pair(va[t].x, va[t].y, h0, l0);
            split_pair(va[t].z, va[t].w, h1, l1);
            *(uint2*)(base + off)                 = make_uint2(h0, h1);
            *(uint2*)(base + BUF_BYTES + off)     = make_uint2(l0, l1);
            split_pair(vb[t].x, vb[t].y, h0, l0);
            split_pair(vb[t].z, vb[t].w, h1, l1);
            *(uint2*)(base + 2 * BUF_BYTES + off) = make_uint2(h0, h1);
            *(uint2*)(base + 3 * BUF_BYTES + off) = make_uint2(l0, l1);
        }
    };

    // ldmatrix lane address components (byte offsets within a buffer)
    // A: row = wm*32 + mi*16 + (L%16), col16 = (L/16)*16B, + ks*32B
    const uint32_t a_row_off = (uint32_t)(wm * 32 + (L & 15)) * PITCHB + ((L >> 4) << 4);
    // B: row n = wn*64 + nj*16 + (L/16)*8 + (L%8), col = ((L>>3)&1)*16B
    const uint32_t b_row_off = (uint32_t)(wn * 64 + ((L >> 4) << 3) + (L & 7)) * PITCHB
                               + (((L >> 3) & 1) << 4);

    auto compute_stage = [&](int stg) {
        const uint32_t base = smb + stg * STAGE_BYTES;
#pragma unroll
        for (int ks = 0; ks < 2; ks++) {
            const uint32_t kso = (uint32_t)(ks << 5);   // 16 bf16 = 32 bytes
            uint32_t ah[2][4], al[2][4], bh[8][2], bl[8][2];
#pragma unroll
            for (int mi = 0; mi < 2; mi++) {
                uint32_t ad = base + a_row_off + (uint32_t)(mi * 16) * PITCHB + kso;
                ldmat_x4(ah[mi], ad);
                ldmat_x4(al[mi], ad + BUF_BYTES);
            }
#pragma unroll
            for (int nj = 0; nj < 4; nj++) {
                uint32_t bd = base + 2 * BUF_BYTES + b_row_off
                              + (uint32_t)(nj * 16) * PITCHB + kso;
                uint32_t r4[4];
                ldmat_x4(r4, bd);
                bh[2 * nj][0] = r4[0]; bh[2 * nj][1] = r4[1];
                bh[2 * nj + 1][0] = r4[2]; bh[2 * nj + 1][1] = r4[3];
                ldmat_x4(r4, bd + BUF_BYTES);
                bl[2 * nj][0] = r4[0]; bl[2 * nj][1] = r4[1];
                bl[2 * nj + 1][0] = r4[2]; bl[2 * nj + 1][1] = r4[3];
            }
#pragma unroll
            for (int mi = 0; mi < 2; mi++)
#pragma unroll
                for (int ni = 0; ni < 8; ni++) {
                    mma_bf16(acc[mi][ni], ah[mi], bh[ni]);
                    mma_bf16(acc[mi][ni], ah[mi], bl[ni]);
                    mma_bf16(acc[mi][ni], al[mi], bh[ni]);
                }
        }
    };

    ldg_stage(0);
    sts_stage(0);
    __syncthreads();
#pragma unroll 1
    for (int kc = 0; kc < NKIT; kc++) {
        if (kc + 1 < NKIT) ldg_stage(kc + 1);
        compute_stage(kc & 1);
        if (kc + 1 < NKIT) sts_stage((kc + 1) & 1);
        __syncthreads();
    }

    // Epilogue: direct fp32 stores (float2 per fragment row)
#pragma unroll
    for (int mi = 0; mi < 2; mi++) {
        int row = m0 + wm * 32 + mi * 16 + (L >> 2);
#pragma unroll
        for (int ni = 0; ni < 8; ni++) {
            int col = n0 + wn * 64 + ni * 8 + ((L & 3) << 1);
            *(float2*)&C[(size_t)row * N + col] =
                make_float2(acc[mi][ni][0], acc[mi][ni][1]);
            *(float2*)&C[(size_t)(row + 8) * N + col] =
                make_float2(acc[mi][ni][2], acc[mi][ni][3]);
        }
    }
}

// ---------------------------------------------------------------------------
// RoPE (in place): q heads rotated + scaled by 1/sqrt(d); k rotated.
// ---------------------------------------------------------------------------
__global__ void rope_kernel()
{
    int t = blockIdx.x * blockDim.x + threadIdx.x;
    const int TOT = BATCH * NSEQ * 17 * 64;
    if (t >= TOT) return;
    int pair = t & 63;
    int unit = (t >> 6) % 17;
    int rest = t / (64 * 17);
    int n = rest % NSEQ;
    int b = rest / NSEQ;

    float invf = powf(10000.f, -(float)(pair << 1) * (1.f / 128.f));
    float ang = (float)n * invf;
    float s, c;
    sincosf(ang, &s, &c);

    float* base;
    float sc;
    if (unit < NH) {
        base = g_qproj + ((size_t)(b * NSEQ + n)) * INNER + unit * DH;
        sc = QK_SCALE;
    } else {
        base = g_kv + ((size_t)(b * NSEQ + n)) * (2 * DH);
        sc = 1.f;
    }
    float x1 = base[pair], x2 = base[pair + 64];
    base[pair]      = (x1 * c - x2 * s) * sc;
    base[pair + 64] = (x2 * c + x1 * s) * sc;
}

// ---------------------------------------------------------------------------
// Causal flash attention (fp32 SIMT), multi-query. BM=BN=128, d=128.
// ---------------------------------------------------------------------------
#define FLASH_SMEM ((2 * 128 * 129 + 128 * 128) * 4)

__global__ __launch_bounds__(256, 1) void flash_kernel()
{
    float* q_s  = fsm;
    float* kp_s = fsm + 128 * 129;
    float* v_s  = fsm + 2 * 128 * 129;

    const int tid = threadIdx.x, tx = tid & 15, ty = tid >> 4;
    const int ib = blockIdx.x, h = blockIdx.y, b = blockIdx.z;
    const int r0 = ib << 7;
    const float* qg  = g_qproj + (size_t)b * NSEQ * INNER + h * DH;
    const float* kvg = g_kv + (size_t)b * NSEQ * (2 * DH);

#pragma unroll
    for (int t = 0; t < 16; t++) {
        int idx = tid + (t << 8);
        int r = idx >> 5, j = idx & 31;
        float4 v = *(const float4*)&qg[(size_t)(r0 + r) * INNER + (j << 2)];
        q_s[((j << 2) + 0) * 129 + r] = v.x;
        q_s[((j << 2) + 1) * 129 + r] = v.y;
        q_s[((j << 2) + 2) * 129 + r] = v.z;
        q_s[((j << 2) + 3) * 129 + r] = v.w;
    }

    float acc[8][8], m_i[8], l_i[8];
#pragma unroll
    for (int i = 0; i < 8; i++) {
        m_i[i] = -INFINITY; l_i[i] = 0.f;
#pragma unroll
        for (int j = 0; j < 8; j++) acc[i][j] = 0.f;
    }

    for (int jb = 0; jb <= ib; jb++) {
        __syncthreads();
        const int c0 = jb << 7;
#pragma unroll
        for (int t = 0; t < 16; t++) {
            int idx = tid + (t << 8);
            int cc = idx >> 5, j = idx & 31;
            float4 v = *(const float4*)&kvg[(size_t)(c0 + cc) * 256 + (j << 2)];
            kp_s[((j << 2) + 0) * 129 + cc] = v.x;
            kp_s[((j << 2) + 1) * 129 + cc] = v.y;
            kp_s[((j << 2) + 2) * 129 + cc] = v.z;
            kp_s[((j << 2) + 3) * 129 + cc] = v.w;
            float4 w = *(const float4*)&kvg[(size_t)(c0 + cc) * 256 + 128 + (j << 2)];
            *(float4*)&v_s[cc * 128 + (j << 2)] = w;
        }
        __syncthreads();

        float s[8][8];
#pragma unroll
        for (int i = 0; i < 8; i++)
#pragma unroll
            for (int j = 0; j < 8; j++) s[i][j] = 0.f;
#pragma unroll 2
        for (int kk = 0; kk < 128; kk++) {
            float a[8], bb[8];
#pragma unroll
            for (int i = 0; i < 8; i++) a[i] = q_s[kk * 129 + ty + (i << 4)];
#pragma unroll
            for (int j = 0; j < 8; j++) bb[j] = kp_s[kk * 129 + tx + (j << 4)];
#pragma unroll
            for (int i = 0; i < 8; i++)
#pragma unroll
                for (int j = 0; j < 8; j++) s[i][j] = fmaf(a[i], bb[j], s[i][j]);
        }
        if (jb == ib) {
#pragma unroll
            for (int i = 0; i < 8; i++)
#pragma unroll
                for (int j = 0; j < 8; j++)
                    if (tx + (j << 4) > ty + (i << 4)) s[i][j] = -1e30f;
        }
#pragma unroll
        for (int i = 0; i < 8; i++) {
            float rm = s[i][0];
#pragma unroll
            for (int j = 1; j < 8; j++) rm = fmaxf(rm, s[i][j]);
#pragma unroll
            for (int o = 1; o < 16; o <<= 1)
                rm = fmaxf(rm, __shfl_xor_sync(0xffffffffu, rm, o));
            float mn = fmaxf(m_i[i], rm);
            float alpha = __expf(m_i[i] - mn);
            m_i[i] = mn;
            float sum = 0.f;
#pragma unroll
            for (int j = 0; j < 8; j++) {
                float p = __expf(s[i][j] - mn);
                s[i][j] = p;
                sum += p;
            }
#pragma unroll
            for (int o = 1; o < 16; o <<= 1)
                sum += __shfl_xor_sync(0xffffffffu, sum, o);
            l_i[i] = l_i[i] * alpha + sum;
#pragma unroll
            for (int j = 0; j < 8; j++) acc[i][j] *= alpha;
        }
        __syncthreads();
#pragma unroll
        for (int j = 0; j < 8; j++)
#pragma unroll
            for (int i = 0; i < 8; i++)
                kp_s[(tx + (j << 4)) * 129 + ty + (i << 4)] = s[i][j];
        __syncthreads();
#pragma unroll 2
        for (int c = 0; c < 128; c++) {
            float pv[8], vv[8];
#pragma unroll
            for (int i = 0; i < 8; i++) pv[i] = kp_s[c * 129 + ty + (i << 4)];
#pragma unroll
            for (int d = 0; d < 8; d++) vv[d] = v_s[c * 128 + tx + (d << 4)];
#pragma unroll
            for (int i = 0; i < 8; i++)
#pragma unroll
                for (int d = 0; d < 8; d++) acc[i][d] = fmaf(pv[i], vv[d], acc[i][d]);
        }
    }
    float* og = g_attn + (size_t)b * NSEQ * INNER + h * DH;
#pragma unroll
    for (int i = 0; i < 8; i++) {
        float inv = 1.f / l_i[i];
        float* orow = &og[(size_t)(r0 + ty + (i << 4)) * INNER];
#pragma unroll
        for (int d = 0; d < 8; d++) orow[tx + (d << 4)] = acc[i][d] * inv;
    }
}

// ---------------------------------------------------------------------------
extern "C" void kernel_launch(void* const* d_in, const int* in_sizes, int n_in,
                              void* d_out, int out_size)
{
    (void)in_sizes; (void)n_in; (void)out_size;
    const float* x    = (const float*)d_in[0];
    const float* Wq   = (const float*)d_in[1];
    const float* Wkv  = (const float*)d_in[2];
    const float* Wout = (const float*)d_in[3];
    float* out = (float*)d_out;

    void *pq, *pkv, *pattn, *pwqt, *pwkvt, *pwoutt;
    cudaGetSymbolAddress(&pq, g_qproj);
    cudaGetSymbolAddress(&pkv, g_kv);
    cudaGetSymbolAddress(&pattn, g_attn);
    cudaGetSymbolAddress(&pwqt, g_WqT);
    cudaGetSymbolAddress(&pwkvt, g_WkvT);
    cudaGetSymbolAddress(&pwoutt, g_WoutT);

    cudaFuncSetAttribute(flash_kernel,
                         cudaFuncAttributeMaxDynamicSharedMemorySize, FLASH_SMEM);
    cudaFuncSetAttribute(gemm_mma,
                         cudaFuncAttributeMaxDynamicSharedMemorySize, GEMM_SMEM);

    const int M = BATCH * NSEQ;  // 4096
    dim3 tb(32, 8);

    // 0) transpose weights to K-major
    transpose_kernel<<<dim3(INNER / 32, DIM / 32), tb>>>(Wq, (float*)pwqt, DIM, INNER);
    transpose_kernel<<<dim3((2 * DH) / 32, DIM / 32), tb>>>(Wkv, (float*)pwkvt, DIM, 2 * DH);
    transpose_kernel<<<dim3(DIM / 32, INNER / 32), tb>>>(Wout, (float*)pwoutt, INNER, DIM);

    // 1) q = x @ Wq
    gemm_mma<<<dim3(INNER / 128, M / 128), 256, GEMM_SMEM>>>(
        x, (const float*)pwqt, (float*)pq, M, INNER);
    // 2) kv = x @ Wkv
    gemm_mma<<<dim3((2 * DH) / 128, M / 128), 256, GEMM_SMEM>>>(
        x, (const float*)pwkvt, (float*)pkv, M, 2 * DH);
    // 3) RoPE in place (+ q scaling)
    {
        int tot = BATCH * NSEQ * 17 * 64;
        rope_kernel<<<(tot + 255) / 256, 256>>>();
    }
    // 4) causal flash attention (fp32 SIMT)
    flash_kernel<<<dim3(NSEQ / 128, NH, BATCH), 256, FLASH_SMEM>>>();
    // 5) out = attn @ Wout
    gemm_mma<<<dim3(DIM / 128, M / 128), 256, GEMM_SMEM>>>(
        (const float*)pattn, (const float*)pwoutt, out, M, DIM);
}

// round 4
// speedup vs baseline: 3.0648x; 1.7727x over previous
#include <cuda_runtime.h>
#include <cuda_bf16.h>
#include <math.h>
#include <cstdint>

#define BATCH 2
#define NSEQ  2048
#define DIM   2048
#define NH    16
#define DH    128
#define INNER 2048
#define KDIM  2048
#define QK_SCALE 0.08838834764831845f  /* 128^-0.5 */

// ---------------------------------------------------------------------------
// Scratch
// ---------------------------------------------------------------------------
__device__ float g_qproj[BATCH * NSEQ * INNER];
__device__ float g_kv[BATCH * NSEQ * 2 * DH];
__device__ float g_attn[BATCH * NSEQ * INNER];
__device__ float g_WqT[DIM * INNER];
__device__ float g_WkvT[2 * DH * DIM];
__device__ float g_WoutT[DIM * INNER];

__device__ __forceinline__ uint32_t smem_u32(const void* p) {
    uint32_t a;
    asm("{ .reg .u64 t; cvta.to.shared.u64 t, %1; cvt.u32.u64 %0, t; }" : "=r"(a) : "l"(p));
    return a;
}
__device__ __forceinline__ void ldmat_x4(uint32_t* r, uint32_t addr) {
    asm volatile("ldmatrix.sync.aligned.m8n8.x4.shared.b16 {%0,%1,%2,%3}, [%4];"
                 : "=r"(r[0]), "=r"(r[1]), "=r"(r[2]), "=r"(r[3]) : "r"(addr));
}
__device__ __forceinline__ void ldmat_x4_t(uint32_t* r, uint32_t addr) {
    asm volatile("ldmatrix.sync.aligned.m8n8.x4.trans.shared.b16 {%0,%1,%2,%3}, [%4];"
                 : "=r"(r[0]), "=r"(r[1]), "=r"(r[2]), "=r"(r[3]) : "r"(addr));
}
__device__ __forceinline__ void mma_bf16(float* d, const uint32_t* a, const uint32_t* b) {
    asm volatile(
        "mma.sync.aligned.m16n8k16.row.col.f32.bf16.bf16.f32 "
        "{%0,%1,%2,%3}, {%4,%5,%6,%7}, {%8,%9}, {%0,%1,%2,%3};"
        : "+f"(d[0]), "+f"(d[1]), "+f"(d[2]), "+f"(d[3])
        : "r"(a[0]), "r"(a[1]), "r"(a[2]), "r"(a[3]), "r"(b[0]), "r"(b[1]));
}
__device__ __forceinline__ uint32_t pack_bf16x2(float x0, float x1) {
    uint32_t r;
    asm("cvt.rn.bf16x2.f32 %0, %1, %2;" : "=r"(r) : "f"(x1), "f"(x0));
    return r;
}
__device__ __forceinline__ void split_pair(float x0, float x1, uint32_t& hi, uint32_t& lo) {
    hi = pack_bf16x2(x0, x1);
    float h0 = __uint_as_float(hi << 16);
    float h1 = __uint_as_float(hi & 0xffff0000u);
    lo = pack_bf16x2(x0 - h0, x1 - h1);
}

// ---------------------------------------------------------------------------
// Weight transpose: in [R, C] -> out [C, R]
// ---------------------------------------------------------------------------
__global__ void transpose_kernel(const float* __restrict__ in, float* __restrict__ out,
                                 int R, int C)
{
    __shared__ float t[32][33];
    int c0 = blockIdx.x << 5, r0 = blockIdx.y << 5;
    int x = threadIdx.x, y = threadIdx.y;
#pragma unroll
    for (int i = 0; i < 32; i += 8)
        t[y + i][x] = in[(size_t)(r0 + y + i) * C + c0 + x];
    __syncthreads();
#pragma unroll
    for (int i = 0; i < 32; i += 8)
        out[(size_t)(c0 + y + i) * R + r0 + x] = t[x][y + i];
}

// ---------------------------------------------------------------------------
// Split-bf16 mma.sync GEMM: C[M,N] = A[M,2048] @ BT[N,2048]^T   (unchanged R3)
// ---------------------------------------------------------------------------
#define PITCHB 80
#define BUF_BYTES (128 * PITCHB)
#define STAGE_BYTES (4 * BUF_BYTES)
#define GEMM_SMEM (2 * STAGE_BYTES)
#define NKIT (KDIM / 32)

extern __shared__ float fsm[];

__global__ __launch_bounds__(256, 1) void gemm_mma(
    const float* __restrict__ A, const float* __restrict__ BT,
    float* __restrict__ C, int M, int N)
{
    char* sm = (char*)fsm;
    const uint32_t smb = smem_u32(sm);
    const int tid = threadIdx.x;
    const int wid = tid >> 5, L = tid & 31;
    const int wm = wid & 3, wn = wid >> 2;
    const int m0 = blockIdx.y << 7, n0 = blockIdx.x << 7;

    const int ldr = tid >> 3;
    const int ldc = tid & 7;

    float acc[2][8][4];
#pragma unroll
    for (int mi = 0; mi < 2; mi++)
#pragma unroll
        for (int ni = 0; ni < 8; ni++)
#pragma unroll
            for (int e = 0; e < 4; e++) acc[mi][ni][e] = 0.f;

    float4 va[4], vb[4];

    auto ldg_stage = [&](int kc) {
#pragma unroll
        for (int t = 0; t < 4; t++) {
            int r = ldr + (t << 5);
            va[t] = *(const float4*)&A[(size_t)(m0 + r) * KDIM + (kc << 5) + (ldc << 2)];
            vb[t] = *(const float4*)&BT[(size_t)(n0 + r) * KDIM + (kc << 5) + (ldc << 2)];
        }
    };
    auto sts_stage = [&](int stg) {
        char* base = sm + stg * STAGE_BYTES;
#pragma unroll
        for (int t = 0; t < 4; t++) {
            int r = ldr + (t << 5);
            uint32_t off = (uint32_t)r * PITCHB + (ldc << 3);
            uint32_t h0, l0, h1, l1;
            split_pair(va[t].x, va[t].y, h0, l0);
            split_pair(va[t].z, va[t].w, h1, l1);
            *(uint2*)(base + off)                 = make_uint2(h0, h1);
            *(uint2*)(base + BUF_BYTES + off)     = make_uint2(l0, l1);
            split_pair(vb[t].x, vb[t].y, h0, l0);
            split_pair(vb[t].z, vb[t].w, h1, l1);
            *(uint2*)(base + 2 * BUF_BYTES + off) = make_uint2(h0, h1);
            *(uint2*)(base + 3 * BUF_BYTES + off) = make_uint2(l0, l1);
        }
    };

    const uint32_t a_row_off = (uint32_t)(wm * 32 + (L & 15)) * PITCHB + ((L >> 4) << 4);
    const uint32_t b_row_off = (uint32_t)(wn * 64 + ((L >> 4) << 3) + (L & 7)) * PITCHB
                               + (((L >> 3) & 1) << 4);

    auto compute_stage = [&](int stg) {
        const uint32_t base = smb + stg * STAGE_BYTES;
#pragma unroll
        for (int ks = 0; ks < 2; ks++) {
            const uint32_t kso = (uint32_t)(ks << 5);
            uint32_t ah[2][4], al[2][4], bh[8][2], bl[8][2];
#pragma unroll
            for (int mi = 0; mi < 2; mi++) {
                uint32_t ad = base + a_row_off + (uint32_t)(mi * 16) * PITCHB + kso;
                ldmat_x4(ah[mi], ad);
                ldmat_x4(al[mi], ad + BUF_BYTES);
            }
#pragma unroll
            for (int nj = 0; nj < 4; nj++) {
                uint32_t bd = base + 2 * BUF_BYTES + b_row_off
                              + (uint32_t)(nj * 16) * PITCHB + kso;
                uint32_t r4[4];
                ldmat_x4(r4, bd);
                bh[2 * nj][0] = r4[0]; bh[2 * nj][1] = r4[1];
                bh[2 * nj + 1][0] = r4[2]; bh[2 * nj + 1][1] = r4[3];
                ldmat_x4(r4, bd + BUF_BYTES);
                bl[2 * nj][0] = r4[0]; bl[2 * nj][1] = r4[1];
                bl[2 * nj + 1][0] = r4[2]; bl[2 * nj + 1][1] = r4[3];
            }
#pragma unroll
            for (int mi = 0; mi < 2; mi++)
#pragma unroll
                for (int ni = 0; ni < 8; ni++) {
                    mma_bf16(acc[mi][ni], ah[mi], bh[ni]);
                    mma_bf16(acc[mi][ni], ah[mi], bl[ni]);
                    mma_bf16(acc[mi][ni], al[mi], bh[ni]);
                }
        }
    };

    ldg_stage(0);
    sts_stage(0);
    __syncthreads();
#pragma unroll 1
    for (int kc = 0; kc < NKIT; kc++) {
        if (kc + 1 < NKIT) ldg_stage(kc + 1);
        compute_stage(kc & 1);
        if (kc + 1 < NKIT) sts_stage((kc + 1) & 1);
        __syncthreads();
    }

#pragma unroll
    for (int mi = 0; mi < 2; mi++) {
        int row = m0 + wm * 32 + mi * 16 + (L >> 2);
#pragma unroll
        for (int ni = 0; ni < 8; ni++) {
            int col = n0 + wn * 64 + ni * 8 + ((L & 3) << 1);
            *(float2*)&C[(size_t)row * N + col] =
                make_float2(acc[mi][ni][0], acc[mi][ni][1]);
            *(float2*)&C[(size_t)(row + 8) * N + col] =
                make_float2(acc[mi][ni][2], acc[mi][ni][3]);
        }
    }
}

// ---------------------------------------------------------------------------
// RoPE (in place)
// ---------------------------------------------------------------------------
__global__ void rope_kernel()
{
    int t = blockIdx.x * blockDim.x + threadIdx.x;
    const int TOT = BATCH * NSEQ * 17 * 64;
    if (t >= TOT) return;
    int pair = t & 63;
    int unit = (t >> 6) % 17;
    int rest = t / (64 * 17);
    int n = rest % NSEQ;
    int b = rest / NSEQ;

    float invf = powf(10000.f, -(float)(pair << 1) * (1.f / 128.f));
    float ang = (float)n * invf;
    float s, c;
    sincosf(ang, &s, &c);

    float* base;
    float sc;
    if (unit < NH) {
        base = g_qproj + ((size_t)(b * NSEQ + n)) * INNER + unit * DH;
        sc = QK_SCALE;
    } else {
        base = g_kv + ((size_t)(b * NSEQ + n)) * (2 * DH);
        sc = 1.f;
    }
    float x1 = base[pair], x2 = base[pair + 64];
    base[pair]      = (x1 * c - x2 * s) * sc;
    base[pair + 64] = (x2 * c + x1 * s) * sc;
}

// ---------------------------------------------------------------------------
// Flash attention with split-bf16 mma.sync.
// CTA: 128 q rows x full KV scan; 8 warps x 16 rows. BN=128, d=128.
// SMEM buffers (bf16, pitch 272B = 136 bf16, conflict-free for ldmatrix):
//   [0] Qh  [1] Ql  [2] Kh  [3] Kl  [4] Vh  [5] Vl
// P stays in registers (C-frag of S == A-frag of PV), split hi/lo.
// ---------------------------------------------------------------------------
#define FB_PITCH 272
#define FB_SIZE (128 * FB_PITCH)           /* 34816 */
#define FLASH_SMEM (6 * FB_SIZE)           /* 208896 */

__global__ __launch_bounds__(256, 1) void flash_mma()
{
    char* sm = (char*)fsm;
    const uint32_t smb = smem_u32(sm);
    const int tid = threadIdx.x;
    const int wid = tid >> 5, L = tid & 31;
    const int ib = blockIdx.x, h = blockIdx.y, b = blockIdx.z;
    const int r0 = ib << 7;
    const int wr0 = wid << 4;

    const float* qg  = g_qproj + (size_t)b * NSEQ * INNER + h * DH;
    const float* kvg = g_kv + (size_t)b * NSEQ * (2 * DH);

    // ---- stage Q (hi/lo bf16), rows r0..r0+127, 128 dims ----
#pragma unroll
    for (int t = 0; t < 16; t++) {
        int idx = tid + (t << 8);
        int r = idx >> 5, c4 = idx & 31;
        float4 v = *(const float4*)&qg[(size_t)(r0 + r) * INNER + (c4 << 2)];
        uint32_t h0, l0, h1, l1;
        split_pair(v.x, v.y, h0, l0);
        split_pair(v.z, v.w, h1, l1);
        uint32_t off = (uint32_t)r * FB_PITCH + (c4 << 3);
        *(uint2*)(sm + off)           = make_uint2(h0, h1);
        *(uint2*)(sm + FB_SIZE + off) = make_uint2(l0, l1);
    }

    // ldmatrix lane address offsets (within a buffer)
    const uint32_t aoff = (uint32_t)(wr0 + (L & 15)) * FB_PITCH + ((L >> 4) << 4);
    const uint32_t koff = (uint32_t)(((L >> 4) << 3) + (L & 7)) * FB_PITCH
                          + (((L >> 3) & 1) << 4);
    const uint32_t voff = (uint32_t)((((L >> 3) & 1) << 3) + (L & 7)) * FB_PITCH
                          + ((L >> 4) << 4);

    float sO[16][4];
    float m_i[2], l_i[2];
#pragma unroll
    for (int nj = 0; nj < 16; nj++)
#pragma unroll
        for (int e = 0; e < 4; e++) sO[nj][e] = 0.f;
    m_i[0] = m_i[1] = -INFINITY;
    l_i[0] = l_i[1] = 0.f;

#pragma unroll 1
    for (int jb = 0; jb <= ib; jb++) {
        __syncthreads();   // prev-iter K/V readers done (also covers Q staging)
        const int c0 = jb << 7;
        // ---- stage K and V tiles (hi/lo bf16) ----
#pragma unroll
        for (int t = 0; t < 16; t++) {
            int idx = tid + (t << 8);
            int r = idx >> 5, c4 = idx & 31;
            const float4* row = (const float4*)&kvg[(size_t)(c0 + r) * 256];
            uint32_t off = (uint32_t)r * FB_PITCH + (c4 << 3);
            float4 kv4 = row[c4];
            uint32_t h0, l0, h1, l1;
            split_pair(kv4.x, kv4.y, h0, l0);
            split_pair(kv4.z, kv4.w, h1, l1);
            *(uint2*)(sm + 2 * FB_SIZE + off) = make_uint2(h0, h1);
            *(uint2*)(sm + 3 * FB_SIZE + off) = make_uint2(l0, l1);
            float4 vv4 = row[32 + c4];
            split_pair(vv4.x, vv4.y, h0, l0);
            split_pair(vv4.z, vv4.w, h1, l1);
            *(uint2*)(sm + 4 * FB_SIZE + off) = make_uint2(h0, h1);
            *(uint2*)(sm + 5 * FB_SIZE + off) = make_uint2(l0, l1);
        }
        __syncthreads();

        // ---- S = Q K^T (3-MMA split) ----
        float s[16][4];
#pragma unroll
        for (int nj = 0; nj < 16; nj++)
#pragma unroll
            for (int e = 0; e < 4; e++) s[nj][e] = 0.f;
#pragma unroll
        for (int ks = 0; ks < 8; ks++) {
            const uint32_t kso = (uint32_t)(ks << 5);
            uint32_t ah[4], al[4];
            ldmat_x4(ah, smb + aoff + kso);
            ldmat_x4(al, smb + FB_SIZE + aoff + kso);
#pragma unroll
            for (int njp = 0; njp < 8; njp++) {
                uint32_t bh4[4], bl4[4];
                uint32_t kd = smb + 2 * FB_SIZE + koff
                              + (uint32_t)(njp * 16) * FB_PITCH + kso;
                ldmat_x4(bh4, kd);
                ldmat_x4(bl4, kd + FB_SIZE);
                mma_bf16(s[2 * njp], ah, bh4);
                mma_bf16(s[2 * njp], ah, bl4);
                mma_bf16(s[2 * njp], al, bh4);
                mma_bf16(s[2 * njp + 1], ah, bh4 + 2);
                mma_bf16(s[2 * njp + 1], ah, bl4 + 2);
                mma_bf16(s[2 * njp + 1], al, bh4 + 2);
            }
        }

        // ---- causal mask (diagonal block: r0 == c0) ----
        if (jb == ib) {
            int rr = L >> 2, cb = (L & 3) << 1;
#pragma unroll
            for (int nj = 0; nj < 16; nj++) {
                int col = nj * 8 + cb;
                int rA = wr0 + rr, rB = rA + 8;
                if (col     > rA) s[nj][0] = -1e30f;
                if (col + 1 > rA) s[nj][1] = -1e30f;
                if (col     > rB) s[nj][2] = -1e30f;
                if (col + 1 > rB) s[nj][3] = -1e30f;
            }
        }

        // ---- online softmax (intra-warp, per row-half) ----
#pragma unroll
        for (int h2 = 0; h2 < 2; h2++) {
            float mx = -INFINITY;
#pragma unroll
            for (int nj = 0; nj < 16; nj++) {
                mx = fmaxf(mx, s[nj][2 * h2]);
                mx = fmaxf(mx, s[nj][2 * h2 + 1]);
            }
            mx = fmaxf(mx, __shfl_xor_sync(0xffffffffu, mx, 1));
            mx = fmaxf(mx, __shfl_xor_sync(0xffffffffu, mx, 2));
            float mn = fmaxf(m_i[h2], mx);
            float alpha = __expf(m_i[h2] - mn);
            m_i[h2] = mn;
            float sum = 0.f;
#pragma unroll
            for (int nj = 0; nj < 16; nj++) {
                float p0 = __expf(s[nj][2 * h2] - mn);
                float p1 = __expf(s[nj][2 * h2 + 1] - mn);
                s[nj][2 * h2] = p0;
                s[nj][2 * h2 + 1] = p1;
                sum += p0 + p1;
            }
            sum += __shfl_xor_sync(0xffffffffu, sum, 1);
            sum += __shfl_xor_sync(0xffffffffu, sum, 2);
            l_i[h2] = l_i[h2] * alpha + sum;
#pragma unroll
            for (int nj = 0; nj < 16; nj++) {
                sO[nj][2 * h2] *= alpha;
                sO[nj][2 * h2 + 1] *= alpha;
            }
        }

        // ---- O += P @ V (P from registers, 3-MMA split; V via ldmatrix.trans) ----
#pragma unroll
        for (int ks = 0; ks < 8; ks++) {
            uint32_t pah[4], pal[4];
            split_pair(s[2 * ks][0], s[2 * ks][1], pah[0], pal[0]);
            split_pair(s[2 * ks][2], s[2 * ks][3], pah[1], pal[1]);
            split_pair(s[2 * ks + 1][0], s[2 * ks + 1][1], pah[2], pal[2]);
            split_pair(s[2 * ks + 1][2], s[2 * ks + 1][3], pah[3], pal[3]);
#pragma unroll
            for (int djp = 0; djp < 8; djp++) {
                uint32_t vh4[4], vl4[4];
                uint32_t vaddr = smb + 4 * FB_SIZE + voff
                                 + (uint32_t)(ks * 16) * FB_PITCH + (uint32_t)(djp * 32);
                ldmat_x4_t(vh4, vaddr);
                ldmat_x4_t(vl4, vaddr + FB_SIZE);
                mma_bf16(sO[2 * djp], pah, vh4);
                mma_bf16(sO[2 * djp], pal, vh4);
                mma_bf16(sO[2 * djp], pah, vl4);
                mma_bf16(sO[2 * djp + 1], pah, vh4 + 2);
                mma_bf16(sO[2 * djp + 1], pal, vh4 + 2);
                mma_bf16(sO[2 * djp + 1], pah, vl4 + 2);
            }
        }
    }

    // ---- epilogue: normalize, write ----
    float* og = g_attn + (size_t)b * NSEQ * INNER + h * DH;
    int rowa = r0 + wr0 + (L >> 2);
#pragma unroll
    for (int h2 = 0; h2 < 2; h2++) {
        float inv = 1.f / l_i[h2];
        float* orow = &og[(size_t)(rowa + 8 * h2) * INNER];
#pragma unroll
        for (int nj = 0; nj < 16; nj++) {
            int col = nj * 8 + ((L & 3) << 1);
            *(float2*)&orow[col] =
                make_float2(sO[nj][2 * h2] * inv, sO[nj][2 * h2 + 1] * inv);
        }
    }
}

// ---------------------------------------------------------------------------
extern "C" void kernel_launch(void* const* d_in, const int* in_sizes, int n_in,
                              void* d_out, int out_size)
{
    (void)in_sizes; (void)n_in; (void)out_size;
    const float* x    = (const float*)d_in[0];
    const float* Wq   = (const float*)d_in[1];
    const float* Wkv  = (const float*)d_in[2];
    const float* Wout = (const float*)d_in[3];
    float* out = (float*)d_out;

    void *pq, *pkv, *pattn, *pwqt, *pwkvt, *pwoutt;
    cudaGetSymbolAddress(&pq, g_qproj);
    cudaGetSymbolAddress(&pkv, g_kv);
    cudaGetSymbolAddress(&pattn, g_attn);
    cudaGetSymbolAddress(&pwqt, g_WqT);
    cudaGetSymbolAddress(&pwkvt, g_WkvT);
    cudaGetSymbolAddress(&pwoutt, g_WoutT);

    cudaFuncSetAttribute(gemm_mma,
                         cudaFuncAttributeMaxDynamicSharedMemorySize, GEMM_SMEM);
    cudaFuncSetAttribute(flash_mma,
                         cudaFuncAttributeMaxDynamicSharedMemorySize, FLASH_SMEM);

    const int M = BATCH * NSEQ;  // 4096
    dim3 tb(32, 8);

    // 0) transpose weights to K-major
    transpose_kernel<<<dim3(INNER / 32, DIM / 32), tb>>>(Wq, (float*)pwqt, DIM, INNER);
    transpose_kernel<<<dim3((2 * DH) / 32, DIM / 32), tb>>>(Wkv, (float*)pwkvt, DIM, 2 * DH);
    transpose_kernel<<<dim3(DIM / 32, INNER / 32), tb>>>(Wout, (float*)pwoutt, INNER, DIM);

    // 1) q = x @ Wq
    gemm_mma<<<dim3(INNER / 128, M / 128), 256, GEMM_SMEM>>>(
        x, (const float*)pwqt, (float*)pq, M, INNER);
    // 2) kv = x @ Wkv
    gemm_mma<<<dim3((2 * DH) / 128, M / 128), 256, GEMM_SMEM>>>(
        x, (const float*)pwkvt, (float*)pkv, M, 2 * DH);
    // 3) RoPE in place (+ q scaling)
    {
        int tot = BATCH * NSEQ * 17 * 64;
        rope_kernel<<<(tot + 255) / 256, 256>>>();
    }
    // 4) causal flash attention (split-bf16 mma)
    flash_mma<<<dim3(NSEQ / 128, NH, BATCH), 256, FLASH_SMEM>>>();
    // 5) out = attn @ Wout
    gemm_mma<<<dim3(DIM / 128, M / 128), 256, GEMM_SMEM>>>(
        (const float*)pattn, (const float*)pwoutt, out, M, DIM);
}